// round 10
// baseline (speedup 1.0000x reference)
#include <cuda_runtime.h>
#include <cuda_fp16.h>
#include <cstdint>

#define NUM_T 64
#define DIN   4096
#define DOUT  11008
#define KS    8
#define KPER  (DIN / KS)     // 512
#define KC    64
#define NCHUNK (KPER / KC)   // 8
#define MT    64
#define NT    128
#define SSTRIDE 72                         // +8 half pad, conflict-free ldmatrix
#define XHALVES (MT * SSTRIDE)             // 4608
#define STAGE_HALVES ((MT + NT) * SSTRIDE) // 13824
#define STAGE_B (STAGE_HALVES * 2)         // 27648
#define SMEM_TOTAL (2 * STAGE_B)           // 55296

// Scratch (allocation-free rule: __device__ globals)
__device__ __align__(256) __half g_xq[NUM_T * DIN];
__device__ __align__(256) float  g_part[KS * NUM_T * DOUT];   // 22.5 MB

// ---------------------------------------------------------------------------
// MXFP4 block constants from amax (integer bit-pattern construction)
// ---------------------------------------------------------------------------
__device__ __forceinline__ void mk_consts(float amax, float& c6s, float& cM,
                                          uint32_t& c2s_bits) {
    if (!(amax > 0.0f)) amax = 1.0f;
    int e  = ((__float_as_int(amax) >> 23) & 0xFF) - 127;
    int se = min(max(e - 2, -127), 127);
    c6s = __int_as_float(((se + 129) << 23) | 0x400000);   // 6 * 2^se
    cM  = __int_as_float((se + 149) << 23);                // 2^(se+22) magic
    c2s_bits = (uint32_t)((se + 128) << 23);               // bits of 2^(se+1)
}

// E2M1 qdq in the t-domain; exactly matches reference (rel_err 0.0 proven).
__device__ __forceinline__ float qdq_fast(float t, float c6s, float cM,
                                          uint32_t c2s_bits) {
    float a = fminf(fabsf(t), c6s);
    uint32_t u = __float_as_uint(a);
    uint32_t r1 = (u + 0x1FFFFFu + ((u >> 22) & 1u)) & 0xFFC00000u;
    float q2 = __fadd_rn(__fadd_rn(a, cM), -cM);
    uint32_t q = (u < c2s_bits) ? __float_as_uint(q2) : r1;
    return __uint_as_float(q | (__float_as_uint(t) & 0x80000000u));
}

// pack two exact f32 values into f16x2 (lo = x, hi = y); conversion exact
__device__ __forceinline__ uint32_t pack_h2(float x, float y) {
    uint32_t r;
    asm("cvt.rn.f16x2.f32 %0, %1, %2;" : "=r"(r) : "f"(y), "f"(x));
    return r;
}

// ---------------------------------------------------------------------------
// x quant-dequant -> f16 (one MXFP block = 8 lanes x float4)
// ---------------------------------------------------------------------------
__global__ void qdq_x_kernel(const float* __restrict__ in) {
    int gtid = blockIdx.x * blockDim.x + threadIdx.x;
    int warp = gtid >> 5;
    int lane = threadIdx.x & 31;
    long base = (long)warp * 128 + (long)lane * 4;
    if (base >= NUM_T * DIN) return;
    float4 v = *reinterpret_cast<const float4*>(in + base);
    float am = fmaxf(fmaxf(fabsf(v.x), fabsf(v.y)), fmaxf(fabsf(v.z), fabsf(v.w)));
    am = fmaxf(am, __shfl_xor_sync(0xffffffffu, am, 1));
    am = fmaxf(am, __shfl_xor_sync(0xffffffffu, am, 2));
    am = fmaxf(am, __shfl_xor_sync(0xffffffffu, am, 4));
    float c6s, cM; uint32_t c2sb;
    mk_consts(am, c6s, cM, c2sb);
    uint2 st;
    st.x = pack_h2(qdq_fast(v.x, c6s, cM, c2sb), qdq_fast(v.y, c6s, cM, c2sb));
    st.y = pack_h2(qdq_fast(v.z, c6s, cM, c2sb), qdq_fast(v.w, c6s, cM, c2sb));
    *reinterpret_cast<uint2*>(&g_xq[base]) = st;
}

// ---------------------------------------------------------------------------
// Fused GEMM: CTA 64M x 128N, 256 thr. One MXFP block (32 W floats) per
// thread per chunk (no shfl); X staged via cp.async; double-buffered.
// ---------------------------------------------------------------------------
#define LDMATRIX_X4(r0, r1, r2, r3, addr)                                        \
    asm volatile("ldmatrix.sync.aligned.m8n8.x4.shared.b16 {%0,%1,%2,%3}, [%4];" \
                 : "=r"(r0), "=r"(r1), "=r"(r2), "=r"(r3) : "r"(addr))

#define MMA16816(c, a0, a1, a2, a3, b0, b1)                                   \
    asm volatile("mma.sync.aligned.m16n8k16.row.col.f32.f16.f16.f32 "         \
                 "{%0,%1,%2,%3}, {%4,%5,%6,%7}, {%8,%9}, {%0,%1,%2,%3};"      \
                 : "+f"(c[0]), "+f"(c[1]), "+f"(c[2]), "+f"(c[3])             \
                 : "r"(a0), "r"(a1), "r"(a2), "r"(a3), "r"(b0), "r"(b1))

__global__ __launch_bounds__(256, 2) void fused_gemm_kernel(const float* __restrict__ W) {
    extern __shared__ __half sm[];   // per stage: X [64][72] then W [128][72]
    int tid  = threadIdx.x;
    int w    = tid >> 5;
    int lane = tid & 31;
    int nbase = blockIdx.x * NT;
    int kbase = blockIdx.y * KPER;
    int mrow  = (w >> 2) * 32;     // 2 M-groups of 32
    int ncol  = (w & 3) * 32;      // 4 N-groups of 32

    float acc[2][4][4];
    #pragma unroll
    for (int i = 0; i < 2; i++)
        #pragma unroll
        for (int j = 0; j < 4; j++)
            #pragma unroll
            for (int k = 0; k < 4; k++) acc[i][j][k] = 0.0f;

    int q = lane >> 3, li = lane & 7;
    uint32_t a_base = (uint32_t)__cvta_generic_to_shared(
        &sm[(mrow + (q & 1) * 8 + li) * SSTRIDE + (q >> 1) * 8]);
    uint32_t b_base = (uint32_t)__cvta_generic_to_shared(
        &sm[XHALVES + (ncol + (q >> 1) * 8 + li) * SSTRIDE + (q & 1) * 8]);

    // W map: 2 threads per row, 32 consecutive floats (one MXFP block) each
    int wrow = tid >> 1;
    int wkb  = (tid & 1) << 5;
    const float* wp = W + (size_t)(nbase + wrow) * DIN + kbase + wkb;
    // X map: 4 threads per row, 16 halves (32B) each, via cp.async
    int xr = tid >> 2, xch = (tid & 3) << 4;
    const __half* xp = g_xq + xr * DIN + kbase + xch;
    uint32_t xdst0 = (uint32_t)__cvta_generic_to_shared(&sm[xr * SSTRIDE + xch]);

    float4 wv[8];

    auto loadw = [&](int c) {
        #pragma unroll
        for (int j = 0; j < 8; j++)
            wv[j] = reinterpret_cast<const float4*>(wp + c * KC)[j];
    };
    auto cpasync_x = [&](int c) {
        uint32_t d = xdst0 + (c & 1) * STAGE_B;
        const __half* s = xp + c * KC;
        asm volatile(
            "cp.async.ca.shared.global [%0], [%1], 16;\n\t"
            "cp.async.ca.shared.global [%2], [%3], 16;\n\t"
            "cp.async.commit_group;"
            :: "r"(d), "l"(s), "r"(d + 16), "l"(s + 8) : "memory");
    };
    auto stagew = [&](int s) {
        float am = 0.0f;
        #pragma unroll
        for (int j = 0; j < 8; j++)
            am = fmaxf(am, fmaxf(fmaxf(fabsf(wv[j].x), fabsf(wv[j].y)),
                                 fmaxf(fabsf(wv[j].z), fabsf(wv[j].w))));
        float c6s, cM; uint32_t c2sb;
        mk_consts(am, c6s, cM, c2sb);   // thread-local: no shfl
        __half* wr = &sm[s * STAGE_HALVES + XHALVES + wrow * SSTRIDE + wkb];
        #pragma unroll
        for (int j = 0; j < 8; j += 2) {
            uint4 st;
            st.x = pack_h2(qdq_fast(wv[j].x,   c6s, cM, c2sb), qdq_fast(wv[j].y,   c6s, cM, c2sb));
            st.y = pack_h2(qdq_fast(wv[j].z,   c6s, cM, c2sb), qdq_fast(wv[j].w,   c6s, cM, c2sb));
            st.z = pack_h2(qdq_fast(wv[j+1].x, c6s, cM, c2sb), qdq_fast(wv[j+1].y, c6s, cM, c2sb));
            st.w = pack_h2(qdq_fast(wv[j+1].z, c6s, cM, c2sb), qdq_fast(wv[j+1].w, c6s, cM, c2sb));
            *reinterpret_cast<uint4*>(wr + j * 4) = st;
        }
    };

    // -------- prologue --------
    loadw(0);
    cpasync_x(0);
    stagew(0);
    loadw(1);
    asm volatile("cp.async.wait_group 0;" ::: "memory");
    __syncthreads();

    // -------- main loop --------
    #pragma unroll 1
    for (int c = 0; c < NCHUNK; c++) {
        if (c + 1 < NCHUNK) {
            cpasync_x(c + 1);            // stage (c+1)&1 was freed by last bar
            stagew((c + 1) & 1);
        }
        if (c + 2 < NCHUNK)
            loadw(c + 2);
        uint32_t off = (c & 1) * STAGE_B;
        #pragma unroll
        for (int ks = 0; ks < 4; ks++) {
            uint32_t A0[4], A1[4], B0[4], B1[4];
            LDMATRIX_X4(A0[0], A0[1], A0[2], A0[3], a_base + off + ks * 32);
            LDMATRIX_X4(A1[0], A1[1], A1[2], A1[3], a_base + off + 16 * SSTRIDE * 2 + ks * 32);
            LDMATRIX_X4(B0[0], B0[1], B0[2], B0[3], b_base + off + ks * 32);
            LDMATRIX_X4(B1[0], B1[1], B1[2], B1[3], b_base + off + 16 * SSTRIDE * 2 + ks * 32);
            #pragma unroll
            for (int i = 0; i < 2; i++) {
                uint32_t* A = i ? A1 : A0;
                MMA16816(acc[i][0], A[0], A[1], A[2], A[3], B0[0], B0[1]);
                MMA16816(acc[i][1], A[0], A[1], A[2], A[3], B0[2], B0[3]);
                MMA16816(acc[i][2], A[0], A[1], A[2], A[3], B1[0], B1[1]);
                MMA16816(acc[i][3], A[0], A[1], A[2], A[3], B1[2], B1[3]);
            }
        }
        asm volatile("cp.async.wait_group 0;" ::: "memory");
        __syncthreads();
    }

    // epilogue: fp32 partials. Warp tile 32x32 at (mrow, nbase+ncol).
    float* pb = g_part + (size_t)blockIdx.y * NUM_T * DOUT;
    int tg = lane >> 2, tig = lane & 3;
    #pragma unroll
    for (int i = 0; i < 2; i++) {
        int r0 = mrow + i * 16 + tg;
        #pragma unroll
        for (int jj = 0; jj < 4; jj++) {
            int col = nbase + ncol + jj * 8 + tig * 2;
            *reinterpret_cast<float2*>(&pb[(size_t)r0 * DOUT + col]) =
                make_float2(acc[i][jj][0], acc[i][jj][1]);
            *reinterpret_cast<float2*>(&pb[(size_t)(r0 + 8) * DOUT + col]) =
                make_float2(acc[i][jj][2], acc[i][jj][3]);
        }
    }
}

// ---------------------------------------------------------------------------
// Reduce K-splits + bias qdq. 1 thread = 1 float4 of output.
// ---------------------------------------------------------------------------
__global__ void reduce_bias_kernel(const float* __restrict__ bias, float* __restrict__ out) {
    int t  = blockIdx.x * blockDim.x + threadIdx.x;
    int m  = t / (DOUT / 4);
    int o  = (t % (DOUT / 4)) * 4;

    float4 b4 = *reinterpret_cast<const float4*>(bias + o);
    float am = fmaxf(fmaxf(fabsf(b4.x), fabsf(b4.y)), fmaxf(fabsf(b4.z), fabsf(b4.w)));
    am = fmaxf(am, __shfl_xor_sync(0xffffffffu, am, 1));
    am = fmaxf(am, __shfl_xor_sync(0xffffffffu, am, 2));
    am = fmaxf(am, __shfl_xor_sync(0xffffffffu, am, 4));
    float c6s, cM; uint32_t c2sb;
    mk_consts(am, c6s, cM, c2sb);

    size_t idx = (size_t)m * DOUT + o;
    const size_t ps = (size_t)NUM_T * DOUT;
    float4 r;
    r.x = qdq_fast(b4.x, c6s, cM, c2sb);
    r.y = qdq_fast(b4.y, c6s, cM, c2sb);
    r.z = qdq_fast(b4.z, c6s, cM, c2sb);
    r.w = qdq_fast(b4.w, c6s, cM, c2sb);
    #pragma unroll
    for (int s = 0; s < KS; s++) {
        float4 p = *reinterpret_cast<const float4*>(g_part + s * ps + idx);
        r.x += p.x; r.y += p.y; r.z += p.z; r.w += p.w;
    }
    *reinterpret_cast<float4*>(out + idx) = r;
}

// ---------------------------------------------------------------------------
extern "C" void kernel_launch(void* const* d_in, const int* in_sizes, int n_in,
                              void* d_out, int out_size) {
    const float* x = nullptr;
    const float* wgt = nullptr;
    const float* bias = nullptr;
    for (int i = 0; i < n_in; i++) {
        if (in_sizes[i] == NUM_T * DIN)     x    = (const float*)d_in[i];
        else if (in_sizes[i] == DOUT * DIN) wgt  = (const float*)d_in[i];
        else if (in_sizes[i] == DOUT)       bias = (const float*)d_in[i];
    }
    float* out = (float*)d_out;

    cudaFuncSetAttribute(fused_gemm_kernel,
                         cudaFuncAttributeMaxDynamicSharedMemorySize, SMEM_TOTAL);

    qdq_x_kernel<<<NUM_T * DIN / 4 / 128, 128>>>(x);
    fused_gemm_kernel<<<dim3(DOUT / NT, KS), 256, SMEM_TOTAL>>>(wgt);
    reduce_bias_kernel<<<(NUM_T * DOUT / 4) / 256, 256>>>(bias, out);
    (void)out_size;
}